// round 17
// baseline (speedup 1.0000x reference)
#include <cuda_runtime.h>
#include <cstdint>

#define B_ 4096
#define S_ 200
#define E_ 128
#define H_ 64
#define G_ 32

// ---- SMEM layout (bytes) --------------------------------------------------
#define KEYS_O   0          // 200 rows x 512B fp32 keys, XOR-32B swizzled ((row&7)<<5)
#define W1T_O    102400     // 64 rows x 512B (hi|lo bf16), resident
#define W2T_O    135168     // 32 rows x 256B (hi|lo bf16), resident
#define QWALL_O  143360     // up to 37 iters x 64 f
#define SC0_O    153600     // score slot 0 (200 f)
#define SC1_O    154400     // score slot 1 (200 f)
#define SCR_O    155200     // consumer scratch (8 f)
#define AP_O     155264     // 3 x 128 f attended partials
#define W3S_O    156800     // 32 f
#define B2S_O    156928     // 32 f
#define B3S_O    157056     // 1 f
#define SMEM_BYTES 157184

// prologue staging (inside KEYS region)
#define PW1_O    0
#define PW2_O    65536
#define PQ_O     73728
#define PB1_O    94208

static __device__ __forceinline__ uint32_t cvta_smem(const void* p) {
    uint32_t a;
    asm("{ .reg .u64 t; cvta.to.shared.u64 t, %1; cvt.u32.u64 %0, t; }" : "=r"(a) : "l"(p));
    return a;
}
static __device__ __forceinline__ uint32_t pk(float lo, float hi) {
    uint32_t r;
    asm("cvt.rn.bf16x2.f32 %0, %1, %2;" : "=r"(r) : "f"(hi), "f"(lo));
    return r;
}
static __device__ __forceinline__ float blo(uint32_t u) { return __uint_as_float(u << 16); }
static __device__ __forceinline__ float bhi(uint32_t u) { return __uint_as_float(u & 0xffff0000u); }

static __device__ __forceinline__ void ldsm4(uint32_t& r0, uint32_t& r1, uint32_t& r2, uint32_t& r3,
                                             uint32_t addr) {
    asm volatile("ldmatrix.sync.aligned.m8n8.x4.shared.b16 {%0,%1,%2,%3}, [%4];"
                 : "=r"(r0), "=r"(r1), "=r"(r2), "=r"(r3) : "r"(addr));
}
static __device__ __forceinline__ void lds64(float& x, float& y, uint32_t addr) {
    asm volatile("ld.shared.v2.f32 {%0,%1}, [%2];" : "=f"(x), "=f"(y) : "r"(addr));
}
static __device__ __forceinline__ void mma_bf16(float* c, const uint32_t* a, uint32_t b0, uint32_t b1) {
    asm volatile("mma.sync.aligned.m16n8k16.row.col.f32.bf16.bf16.f32 "
                 "{%0,%1,%2,%3}, {%4,%5,%6,%7}, {%8,%9}, {%0,%1,%2,%3};"
                 : "+f"(c[0]), "+f"(c[1]), "+f"(c[2]), "+f"(c[3])
                 : "r"(a[0]), "r"(a[1]), "r"(a[2]), "r"(a[3]), "r"(b0), "r"(b1));
}

#define CPA(sm, g) asm volatile("cp.async.cg.shared.global [%0], [%1], 16;" :: "r"(sm), "l"(g))
#define CPC()      asm volatile("cp.async.commit_group;" ::: "memory")
#define CPW(n)     asm volatile("cp.async.wait_group %0;" :: "n"(n) : "memory")

// named barriers: 1,2 = scores-ready (parity), 3,4 = slot-free (parity), 7 = consumer-local
#define BSYNC(id)   asm volatile("bar.sync %0, 512;"   :: "r"(id) : "memory")
#define BARRIVE(id) asm volatile("bar.arrive %0, 512;" :: "r"(id) : "memory")
#define MEMBAR()    asm volatile("membar.cta;" ::: "memory")
#define CBAR()      asm volatile("bar.sync 7, 96;" ::: "memory")

__global__ __launch_bounds__(512, 1)
void attn_persist_kernel(const float* __restrict__ query,
                         const float* __restrict__ keys,
                         const int*   __restrict__ mask,
                         const float* __restrict__ W1,
                         const float* __restrict__ b1,
                         const float* __restrict__ W2,
                         const float* __restrict__ b2,
                         const float* __restrict__ W3,
                         const float* __restrict__ b3,
                         float* __restrict__ out)
{
    extern __shared__ char smb[];
    const uint32_t sb = cvta_smem(smb);
    const int t    = threadIdx.x;
    const int warp = t >> 5;
    const int lane = t & 31;
    const int grid = gridDim.x;
    const int nb   = (B_ - blockIdx.x + grid - 1) / grid;

    // ================= Prologue (all 512 threads) =================
    {
        #pragma unroll 4
        for (int i = t; i < 4096; i += 512) CPA(sb + PW1_O + i * 16, (const char*)W1 + i * 16);
        CPA(sb + PW2_O + t * 16, (const char*)W2 + t * 16);
        for (int j = t; j < nb * 32; j += 512) {
            const int bi = blockIdx.x + (j >> 5) * grid;
            CPA(sb + PQ_O + j * 16, (const char*)(query + (size_t)bi * E_) + (j & 31) * 16);
        }
        if (t < 16) CPA(sb + PB1_O + t * 16, (const char*)b1 + t * 16);
        if (t < 8)  CPA(sb + W3S_O + t * 16, (const char*)W3 + t * 16);
        if (t < 8)  CPA(sb + B2S_O + t * 16, (const char*)b2 + t * 16);
        CPC();
    }
    CPW(0);
    if (t == 0) ((float*)(smb + B3S_O))[0] = b3[0];
    __syncthreads();

    // W1T (rows 128..255 of W1) hi/lo bf16, swizzled
    {
        const float* stg = (const float*)(smb + PW1_O + 32768);
        #pragma unroll
        for (int p = t; p < 4096; p += 512) {
            const int n  = p & 63;
            const int kp = p >> 6;
            const float a = stg[(2 * kp) * H_ + n];
            const float c = stg[(2 * kp + 1) * H_ + n];
            const uint32_t hu = pk(a, c);
            const uint32_t lu = pk(a - blo(hu), c - bhi(hu));
            char* dst = smb + W1T_O + n * 512 + (((uint32_t)(kp * 4)) ^ ((n & 7) << 4));
            *(uint32_t*)dst = hu;
            *(uint32_t*)(dst + 256) = lu;
        }
    }
    // W2T hi/lo bf16, swizzled
    {
        const float* stg2 = (const float*)(smb + PW2_O);
        #pragma unroll
        for (int p = t; p < 1024; p += 512) {
            const int g  = p & 31;
            const int hp = p >> 5;
            const float a = stg2[(2 * hp) * G_ + g];
            const float c = stg2[(2 * hp + 1) * G_ + g];
            const uint32_t hu = pk(a, c);
            const uint32_t lu = pk(a - blo(hu), c - bhi(hu));
            char* dst = smb + W2T_O + g * 256 + (((uint32_t)(hp * 4)) ^ ((g & 7) << 4));
            *(uint32_t*)dst = hu;
            *(uint32_t*)(dst + 128) = lu;
        }
    }
    // qw[i][h] for all assigned b's
    {
        const float* w1top = (const float*)(smb + PW1_O);
        const float* b1f   = (const float*)(smb + PB1_O);
        const int h    = t & 63;
        const int isub = t >> 6;
        for (int i0 = 0; i0 < nb; i0 += 8) {
            const int i = i0 + isub;
            if (i < nb) {
                const float* q = (const float*)(smb + PQ_O) + i * 128;
                float s = b1f[h];
                #pragma unroll 8
                for (int e = 0; e < 128; ++e) s = fmaf(q[e], w1top[e * 64 + h], s);
                ((float*)(smb + QWALL_O))[i * 64 + h] = s;
            }
        }
    }
    __syncthreads();

    // producers: fetch own rows of first keys tile, fp32, XOR-32B swizzled dst
    if (warp < 13) {
        const int m0 = warp * 16;
        const int nrows = (m0 + 16 <= S_) ? 16 : (S_ - m0);
        const char* gk = (const char*)keys + ((size_t)blockIdx.x * (S_ * E_) + (size_t)m0 * E_) * 4;
        #pragma unroll 4
        for (int c = lane; c < nrows * 32; c += 32) {
            const int row = m0 + (c >> 5);
            const uint32_t dst = sb + KEYS_O + row * 512 +
                                 (((uint32_t)((c & 31) * 16)) ^ ((uint32_t)((row & 7) << 5)));
            CPA(dst, gk + (size_t)c * 16);
        }
        CPC();
    }
    // NOTE: no barrier priming (producers skipping BSYNC(slot) for it<2 IS the priming).

    const int r0 = lane >> 2;
    const int cb = (lane & 3) * 2;

    // B-operand ldmatrix addressing (layers 1 and 2):
    const int      brow  = (lane & 7) + ((lane >> 4) << 3);
    const uint32_t bkoff = (uint32_t)(((lane >> 3) & 1) << 4);
    const uint32_t bxv   = (uint32_t)((lane & 7) << 4);
    const uint32_t bsel  = bkoff ^ (bxv & 0x10);
    const uint32_t bxhi  = bxv & 0x60;

    // A-operand fp32 LDS addressing (layer 1):
    const uint32_t asw = (uint32_t)(((lane >> 2) & 7) << 5);     // row XOR-32B swizzle
    const uint32_t acq = (uint32_t)((lane & 3) * 8);             // byte of fp32 pair 2(lane&3)

    // ================= Main loop =================
    for (int it = 0; it < nb; ++it) {
        const int b = blockIdx.x + it * grid;
        float* scf = (float*)(smb + ((it & 1) ? SC1_O : SC0_O));

        if (warp < 13) {
            // ======== PRODUCER: warps 0-12 ========
            CPW(0);              // own keys prefetch landed
            const int m0 = warp * 16;

            // mask for this warp's two rows via LDG (consumed much later)
            int mA = 1, mB = 1;
            {
                const int rowA_ = m0 + r0, rowB_ = rowA_ + 8;
                const int* gm = mask + (size_t)b * S_;
                if ((lane & 3) == 0) {
                    if (rowA_ < S_) mA = gm[rowA_];
                    if (rowB_ < S_) mB = gm[rowB_];
                }
            }

            // ---- Layer 1: A = fp32 keys via LDS.64, split to bf16 hi/lo in regs ----
            float acc[8][4];
            #pragma unroll
            for (int n = 0; n < 8; ++n)
                #pragma unroll
                for (int j = 0; j < 4; ++j) acc[n][j] = 0.f;

            const uint32_t rowAb = sb + KEYS_O + (m0 + (lane >> 2)) * 512;
            const uint32_t rowBb = rowAb + 8 * 512;
            const uint32_t bbase1 = sb + W1T_O + brow * 512 + bsel;

            #pragma unroll
            for (int k = 0; k < 8; ++k) {
                const uint32_t c0 = ((uint32_t)(64 * k) + acq) ^ asw;
                const uint32_t c1 = ((uint32_t)(64 * k + 32) + acq) ^ asw;
                float x0, y0, x1, y1, x2, y2, x3, y3;
                lds64(x0, y0, rowAb + c0);
                lds64(x1, y1, rowBb + c0);
                lds64(x2, y2, rowAb + c1);
                lds64(x3, y3, rowBb + c1);
                uint32_t ah[4], al[4];
                ah[0] = pk(x0, y0); al[0] = pk(x0 - blo(ah[0]), y0 - bhi(ah[0]));
                ah[1] = pk(x1, y1); al[1] = pk(x1 - blo(ah[1]), y1 - bhi(ah[1]));
                ah[2] = pk(x2, y2); al[2] = pk(x2 - blo(ah[2]), y2 - bhi(ah[2]));
                ah[3] = pk(x3, y3); al[3] = pk(x3 - blo(ah[3]), y3 - bhi(ah[3]));

                const uint32_t kc = ((uint32_t)(k * 32)) ^ bxhi;
                #pragma unroll
                for (int j = 0; j < 4; ++j) {
                    uint32_t bh[4], bl[4];
                    const uint32_t ba = bbase1 + (uint32_t)(j * 8192) + kc;
                    ldsm4(bh[0], bh[1], bh[2], bh[3], ba);
                    ldsm4(bl[0], bl[1], bl[2], bl[3], ba + 256);
                    mma_bf16(acc[2 * j],     ah, bh[0], bh[1]);
                    mma_bf16(acc[2 * j],     ah, bl[0], bl[1]);
                    mma_bf16(acc[2 * j],     al, bh[0], bh[1]);
                    mma_bf16(acc[2 * j + 1], ah, bh[2], bh[3]);
                    mma_bf16(acc[2 * j + 1], ah, bl[2], bl[3]);
                    mma_bf16(acc[2 * j + 1], al, bh[2], bh[3]);
                }
            }

            // ---- early warp-local prefetch of next b's own key rows (swizzled) ----
            if (it + 1 < nb) {
                const int bn = b + grid;
                const int nrows = (m0 + 16 <= S_) ? 16 : (S_ - m0);
                const char* gk = (const char*)keys +
                                 ((size_t)bn * (S_ * E_) + (size_t)m0 * E_) * 4;
                #pragma unroll 4
                for (int c = lane; c < nrows * 32; c += 32) {
                    const int row = m0 + (c >> 5);
                    const uint32_t dst = sb + KEYS_O + row * 512 +
                                         (((uint32_t)((c & 31) * 16)) ^ ((uint32_t)((row & 7) << 5)));
                    CPA(dst, gk + (size_t)c * 16);
                }
                CPC();
            }

            // ---- epilogue -> A-fragments for layer 2 ----
            uint32_t ahf[4][4], alf[4][4];
            const float* qwf = (const float*)(smb + QWALL_O) + it * 64;
            #pragma unroll
            for (int kt = 0; kt < 4; ++kt) {
                #pragma unroll
                for (int half = 0; half < 2; ++half) {
                    const int n = 2 * kt + half;
                    const int c = n * 8 + cb;
                    const float qa = qwf[c], qb = qwf[c + 1];
                    const float v0 = fmaxf(acc[n][0] + qa, 0.f);
                    const float v1 = fmaxf(acc[n][1] + qb, 0.f);
                    const float v2 = fmaxf(acc[n][2] + qa, 0.f);
                    const float v3 = fmaxf(acc[n][3] + qb, 0.f);
                    const uint32_t h01 = pk(v0, v1), h23 = pk(v2, v3);
                    ahf[kt][2 * half]     = h01;
                    ahf[kt][2 * half + 1] = h23;
                    alf[kt][2 * half]     = pk(v0 - blo(h01), v1 - bhi(h01));
                    alf[kt][2 * half + 1] = pk(v2 - blo(h23), v3 - bhi(h23));
                }
            }

            // ---- Layer 2 (B via ldmatrix.x4) ----
            float acc2[4][4];
            #pragma unroll
            for (int n = 0; n < 4; ++n)
                #pragma unroll
                for (int j = 0; j < 4; ++j) acc2[n][j] = 0.f;

            const uint32_t bbase2 = sb + W2T_O + brow * 256 + bsel;
            #pragma unroll
            for (int kt = 0; kt < 4; ++kt) {
                const uint32_t kc = ((uint32_t)(kt * 32)) ^ bxhi;
                #pragma unroll
                for (int j = 0; j < 2; ++j) {
                    uint32_t bh[4], bl[4];
                    const uint32_t ba = bbase2 + (uint32_t)(j * 4096) + kc;
                    ldsm4(bh[0], bh[1], bh[2], bh[3], ba);
                    ldsm4(bl[0], bl[1], bl[2], bl[3], ba + 128);
                    mma_bf16(acc2[2 * j],     ahf[kt], bh[0], bh[1]);
                    mma_bf16(acc2[2 * j],     ahf[kt], bl[0], bl[1]);
                    mma_bf16(acc2[2 * j],     alf[kt], bh[0], bh[1]);
                    mma_bf16(acc2[2 * j + 1], ahf[kt], bh[2], bh[3]);
                    mma_bf16(acc2[2 * j + 1], ahf[kt], bl[2], bl[3]);
                    mma_bf16(acc2[2 * j + 1], alf[kt], bh[2], bh[3]);
                }
            }

            // ---- Layer 3 ----
            const float* b2f = (const float*)(smb + B2S_O);
            const float* w3f = (const float*)(smb + W3S_O);
            float p0 = 0.f, p8 = 0.f;
            #pragma unroll
            for (int n = 0; n < 4; ++n) {
                const int c = n * 8 + cb;
                const float w3a = w3f[c], w3b = w3f[c + 1];
                const float ba = b2f[c],  bb = b2f[c + 1];
                p0 = fmaf(fmaxf(acc2[n][0] + ba, 0.f), w3a,
                     fmaf(fmaxf(acc2[n][1] + bb, 0.f), w3b, p0));
                p8 = fmaf(fmaxf(acc2[n][2] + ba, 0.f), w3a,
                     fmaf(fmaxf(acc2[n][3] + bb, 0.f), w3b, p8));
            }
            p0 += __shfl_xor_sync(0xffffffffu, p0, 1);
            p0 += __shfl_xor_sync(0xffffffffu, p0, 2);
            p8 += __shfl_xor_sync(0xffffffffu, p8, 1);
            p8 += __shfl_xor_sync(0xffffffffu, p8, 2);

            // wait until consumers freed this score slot (iter it-2)
            if (it >= 2) BSYNC(3 + (it & 1));

            if ((lane & 3) == 0) {
                const int rowA = m0 + r0;
                const int rowB = rowA + 8;
                const float b3v = ((const float*)(smb + B3S_O))[0];
                if (rowA < S_) {
                    float sc = p0 + b3v;
                    if (mA == 0) sc = -1e9f;
                    scf[rowA] = sc;
                }
                if (rowB < S_) {
                    float sc = p8 + b3v;
                    if (mB == 0) sc = -1e9f;
                    scf[rowB] = sc;
                }
            }
            MEMBAR();                 // publish score writes before arrive
            BARRIVE(1 + (it & 1));    // scores(it) ready

        } else {
            // ======== CONSUMER: warps 13-15 (96 threads) ========
            const int tc = t - 416;           // 0..95
            const int cwarp = tc >> 5;        // 0..2
            float* scr = (float*)(smb + SCR_O);

            BSYNC(1 + (it & 1));              // wait scores(it)

            // max
            float v0 = scf[tc];
            float v1 = scf[tc + 96];
            float v2 = (tc < 8) ? scf[tc + 192] : -3e38f;
            float mx = fmaxf(fmaxf(v0, v1), v2);
            #pragma unroll
            for (int o = 16; o; o >>= 1) mx = fmaxf(mx, __shfl_xor_sync(0xffffffffu, mx, o));
            if ((tc & 31) == 0) scr[cwarp] = mx;
            CBAR();
            mx = fmaxf(scr[0], fmaxf(scr[1], scr[2]));

            // exp + sum (scf becomes unnormalized exp)
            const float e0 = __expf(v0 - mx);
            const float e1 = __expf(v1 - mx);
            const float e2 = (tc < 8) ? __expf(v2 - mx) : 0.f;
            scf[tc] = e0;
            scf[tc + 96] = e1;
            if (tc < 8) scf[tc + 192] = e2;
            float ps = e0 + e1 + e2;
            #pragma unroll
            for (int o = 16; o; o >>= 1) ps += __shfl_xor_sync(0xffffffffu, ps, o);
            if ((tc & 31) == 0) scr[3 + cwarp] = ps;
            CBAR();                            // also publishes all exp writes
            const float inv = 1.0f / (scr[3] + scr[4] + scr[5]);

            // weights out
            {
                float* out_w = out + (size_t)B_ * E_ + (size_t)b * S_;
                out_w[tc] = e0 * inv;
                out_w[tc + 96] = e1 * inv;
                if (tc < 8) out_w[tc + 192] = e2 * inv;
            }

            // attended: 3 partitions x ~67 s, float4 keys (L2-hot)
            {
                const int col = tc & 31;      // float4 column
                const float4* kg = (const float4*)(keys + (size_t)b * (S_ * E_)) + col;
                float a0 = 0.f, a1 = 0.f, a2 = 0.f, a3 = 0.f;
                const int sbeg = cwarp * 67;
                const int send = (cwarp == 2) ? S_ : sbeg + 67;
                #pragma unroll 4
                for (int s = sbeg; s < send; ++s) {
                    const float4 kv = kg[(size_t)s * 32];
                    const float w = scf[s];
                    a0 = fmaf(w, kv.x, a0);
                    a1 = fmaf(w, kv.y, a1);
                    a2 = fmaf(w, kv.z, a2);
                    a3 = fmaf(w, kv.w, a3);
                }
                ((float4*)(smb + AP_O))[cwarp * 32 + col] = make_float4(a0, a1, a2, a3);
            }
            CBAR();
            {
                const float* apf = (const float*)(smb + AP_O);
                float* ob = out + (size_t)b * E_;
                {
                    const int e = tc;
                    ob[e] = (apf[e] + apf[128 + e] + apf[256 + e]) * inv;
                }
                if (tc < 32) {
                    const int e = tc + 96;
                    ob[e] = (apf[e] + apf[128 + e] + apf[256 + e]) * inv;
                }
            }
            MEMBAR();                         // order scf reads/AP writes before release
            BARRIVE(3 + (it & 1));            // slot(it) free
        }
    }
}

extern "C" void kernel_launch(void* const* d_in, const int* in_sizes, int n_in,
                              void* d_out, int out_size) {
    const float* query = (const float*)d_in[0];
    const float* keys  = (const float*)d_in[1];
    const int*   mask  = (const int*)d_in[2];
    const float* W1    = (const float*)d_in[3];
    const float* b1    = (const float*)d_in[4];
    const float* W2    = (const float*)d_in[5];
    const float* b2    = (const float*)d_in[6];
    const float* W3    = (const float*)d_in[7];
    const float* b3    = (const float*)d_in[8];
    float* out = (float*)d_out;

    int nsm = 148;
    cudaDeviceGetAttribute(&nsm, cudaDevAttrMultiProcessorCount, 0);
    if (nsm < 112)  nsm = 112;
    if (nsm > 1024) nsm = 1024;

    cudaFuncSetAttribute(attn_persist_kernel,
                         cudaFuncAttributeMaxDynamicSharedMemorySize, SMEM_BYTES);
    attn_persist_kernel<<<nsm, 512, SMEM_BYTES>>>(query, keys, mask, W1, b1, W2, b2, W3, b3, out);
}